// round 1
// baseline (speedup 1.0000x reference)
#include <cuda_runtime.h>

// ive(v=49.5, z) = exp(-z) I_v(z) via rescaled ascending series, evaluated as a
// Horner polynomial in w = (z^2/4)/M with compile-time coefficients b_k = a_k M^k.
// Series sum S = sum_k b_k w^k equals the reference's scaled series exactly.
// Truncated at K=64 terms (tail < 1e-8 relative for z <= 99.5).
//
// Hot loop uses packed fma.rn.f32x2 (FFMA2): 1 instruction = 2 fp32 FMAs,
// restoring full-rate fp32 on sm_103a (FFMA-3reg is half-rate).

#define KT 64

constexpr double MSCALE_D = 2500.0;           // rescale so coefficients stay in fp32 range
constexpr float  WC       = 0.25f / 2500.0f;  // w = z*z * WC
constexpr float  VORD     = 49.5f;
constexpr float  LGAMMA_VP1 = 146.5192555f;   // lgamma(50.5)

struct BTab { float2 b[KT + 1]; };

constexpr BTab make_btab() {
    BTab t{};
    double a = 1.0;
    t.b[0] = float2{1.0f, 1.0f};
    for (int k = 1; k <= KT; k++) {
        a *= MSCALE_D / ((double)k * (49.5 + (double)k));
        float f = (float)a;
        t.b[k] = float2{f, f};
    }
    return t;
}

__constant__ BTab c_btab = make_btab();

// ---- packed f32x2 helpers ----
__device__ __forceinline__ unsigned long long pack2(float a, float b) {
    unsigned long long r;
    asm("mov.b64 %0, {%1, %2};" : "=l"(r) : "f"(a), "f"(b));
    return r;
}
__device__ __forceinline__ void unpack2(unsigned long long v, float& a, float& b) {
    asm("mov.b64 {%0, %1}, %2;" : "=f"(a), "=f"(b) : "l"(v));
}
__device__ __forceinline__ unsigned long long fma2(unsigned long long a,
                                                   unsigned long long b,
                                                   unsigned long long c) {
    unsigned long long d;
    asm("fma.rn.f32x2 %0, %1, %2, %3;" : "=l"(d) : "l"(a), "l"(b), "l"(c));
    return d;
}

// prefactor: exp(v*log(z/2) - lgamma(v+1) - z) * S
__device__ __forceinline__ float ive_finish(float z, float s) {
    float lp = fmaf(VORD, __logf(0.5f * z), -LGAMMA_VP1) - z;
    return __expf(lp) * s;   // underflows to 0 exactly like the fp32 reference
}

__global__ void __launch_bounds__(256)
ive_kernel(const float* __restrict__ zin, float* __restrict__ out, int n) {
    long long base = ((long long)blockIdx.x * 256 + threadIdx.x) * 8;
    if (base + 8 <= (long long)n) {
        float4 a = *reinterpret_cast<const float4*>(zin + base);
        float4 b = *reinterpret_cast<const float4*>(zin + base + 4);
        float zv[8] = {a.x, a.y, a.z, a.w, b.x, b.y, b.z, b.w};

        unsigned long long W[4], S[4];
#pragma unroll
        for (int i = 0; i < 4; i++) {
            float w0 = zv[2 * i]     * zv[2 * i]     * WC;
            float w1 = zv[2 * i + 1] * zv[2 * i + 1] * WC;
            W[i] = pack2(w0, w1);
        }
        {
            float2 bt = c_btab.b[KT];
            unsigned long long st = pack2(bt.x, bt.y);
            S[0] = st; S[1] = st; S[2] = st; S[3] = st;
        }

        // Horner: s = s*w + b_k, one FFMA2 per term per 2 elements.
#pragma unroll
        for (int k = KT - 1; k >= 0; k--) {
            float2 bk = c_btab.b[k];
            unsigned long long bb = pack2(bk.x, bk.y);
            S[0] = fma2(S[0], W[0], bb);
            S[1] = fma2(S[1], W[1], bb);
            S[2] = fma2(S[2], W[2], bb);
            S[3] = fma2(S[3], W[3], bb);
        }

        float r[8];
#pragma unroll
        for (int i = 0; i < 4; i++) {
            float s0, s1;
            unpack2(S[i], s0, s1);
            r[2 * i]     = ive_finish(zv[2 * i],     s0);
            r[2 * i + 1] = ive_finish(zv[2 * i + 1], s1);
        }
        *reinterpret_cast<float4*>(out + base)     = make_float4(r[0], r[1], r[2], r[3]);
        *reinterpret_cast<float4*>(out + base + 4) = make_float4(r[4], r[5], r[6], r[7]);
    } else {
        long long end = ((long long)n < base + 8) ? (long long)n : base + 8;
        for (long long i = base; i < end; i++) {
            float zz = zin[i];
            float w  = zz * zz * WC;
            float s  = c_btab.b[KT].x;
            for (int k = KT - 1; k >= 0; k--)
                s = fmaf(s, w, c_btab.b[k].x);
            out[i] = ive_finish(zz, s);
        }
    }
}

extern "C" void kernel_launch(void* const* d_in, const int* in_sizes, int n_in,
                              void* d_out, int out_size) {
    const float* z = (const float*)d_in[0];
    float* out = (float*)d_out;
    int n = in_sizes[0];
    if (n <= 0) return;
    int per_block = 256 * 8;
    int grid = (n + per_block - 1) / per_block;
    ive_kernel<<<grid, 256>>>(z, out, n);
}

// round 3
// speedup vs baseline: 1.6315x; 1.6315x over previous
#include <cuda_runtime.h>
#include <cmath>

// ive(v=49.5, z) = exp( v*ln(z/2) - lgamma(v+1) - z + lnS(z^2) )
// where S(s) = sum_k (s/4)^k / (k! (v+1)_k),  I_v(z) = (z/2)^v/Gamma(v+1) * S(z^2).
//
// lnS(s) is analytic on s in [0.25, 9900.25]; nearest singularity (first zero of S,
// s = -j_{v,1}^2 ~ -3203) gives degree-24 Taylor about the range center an error
// ~5e-7. Coefficients are computed ON THE HOST at static init (double precision,
// std::log / std::lgamma) and passed to the kernel BY VALUE (constant bank) —
// avoiding nvcc's __constant__ constexpr-init limits that killed round 2.
//
// Runtime per element: out = ex2( 24.75*lg2(s) + P(t) - z/ln2 ), t=(s-s0)/h,
// P = 24-step Horner in packed fma.rn.f32x2 (2 elements per instruction).

#define NP   24
#define KMAX 320
#define TPB  256
#define EPT  8

struct QTab { float q[NP + 1]; };

static QTab make_q_host() {
    const double VD = 49.5, S0D = 4950.25, HSD = 4950.0;
    const double LN2D = 0.69314718055994530942;
    // 1) Taylor coeffs of S about s0, in t=(s-s0)/HSD:
    //    pt[m] = (h/s0)^m * sum_{k>=m} C(k,m) * T_k,  T_k = (s0/4)^k/(k! (v+1)_k)
    double pt[NP + 1];
    for (int m = 0; m <= NP; m++) {
        double sum = 0.0, T = 1.0, binom = 1.0;
        for (int k = 0; k <= KMAX; k++) {
            if (k > 0) T = T * S0D / (4.0 * (double)k * (VD + (double)k));
            if (k > m) binom = binom * (double)k / (double)(k - m);
            if (k >= m) sum += binom * T;
        }
        double hm = 1.0;
        for (int i = 0; i < m; i++) hm *= HSD / S0D;
        pt[m] = sum * hm;
    }
    // 2) log-of-power-series recurrence: Taylor of lnS
    double u[NP + 1] = {0}, q[NP + 1];
    for (int m = 1; m <= NP; m++) u[m] = pt[m] / pt[0];
    q[0] = std::log(pt[0]);
    for (int m = 1; m <= NP; m++) {
        double acc = u[m];
        for (int j = 1; j < m; j++) acc -= (double)j * q[j] * u[m - j] / (double)m;
        q[m] = acc;
    }
    // 3) fold constants; convert to log2 units. Note v*ln(z/2)/ln2 = 24.75*lg2(s) - v.
    double lg = std::lgamma(50.5);
    QTab t;
    for (int m = 0; m <= NP; m++) t.q[m] = (float)(q[m] / LN2D);
    t.q[0] = (float)((q[0] - lg) / LN2D - VD);
    return t;
}
static const QTab H_Q = make_q_host();   // host static init — no device side effects

// ---- packed f32x2 + MUFU helpers ----
__device__ __forceinline__ unsigned long long pack2(float a, float b) {
    unsigned long long r;
    asm("mov.b64 %0, {%1, %2};" : "=l"(r) : "f"(a), "f"(b));
    return r;
}
__device__ __forceinline__ void unpack2(unsigned long long v, float& a, float& b) {
    asm("mov.b64 {%0, %1}, %2;" : "=f"(a), "=f"(b) : "l"(v));
}
__device__ __forceinline__ unsigned long long fma2(unsigned long long a,
                                                   unsigned long long b,
                                                   unsigned long long c) {
    unsigned long long d;
    asm("fma.rn.f32x2 %0, %1, %2, %3;" : "=l"(d) : "l"(a), "l"(b), "l"(c));
    return d;
}
__device__ __forceinline__ unsigned long long mul2(unsigned long long a,
                                                   unsigned long long b) {
    unsigned long long d;
    asm("mul.rn.f32x2 %0, %1, %2;" : "=l"(d) : "l"(a), "l"(b));
    return d;
}
__device__ __forceinline__ float lg2f(float x) {
    float r; asm("lg2.approx.f32 %0, %1;" : "=f"(r) : "f"(x)); return r;
}
__device__ __forceinline__ float ex2f(float x) {
    float r; asm("ex2.approx.f32 %0, %1;" : "=f"(r) : "f"(x)); return r;
}

__global__ void __launch_bounds__(TPB)
ive_kernel(const float* __restrict__ zin, float* __restrict__ out, int n, QTab tab) {
    __shared__ float2 qs[NP + 1];
    if (threadIdx.x <= NP) {
        float v = tab.q[threadIdx.x];    // LDC from param (constant bank)
        qs[threadIdx.x] = make_float2(v, v);
    }
    __syncthreads();

    const float HIF = 1.0f / 4950.0f;
    const float HCF = -4950.25f / 4950.0f;
    const unsigned long long HI2  = pack2(HIF, HIF);
    const unsigned long long HC2  = pack2(HCF, HCF);
    const unsigned long long NIL2 = pack2(-1.44269504088896341f, -1.44269504088896341f);

    long long base = ((long long)blockIdx.x * TPB + threadIdx.x) * EPT;
    if (base + EPT <= (long long)n) {
        float4 a = __ldcs((const float4*)(zin + base));
        float4 b = __ldcs((const float4*)(zin + base + 4));
        unsigned long long Z[4] = {pack2(a.x, a.y), pack2(a.z, a.w),
                                   pack2(b.x, b.y), pack2(b.z, b.w)};
        unsigned long long S[4], T[4], R[4];
        {
            float2 qt = qs[NP];
            unsigned long long Qt = pack2(qt.x, qt.y);
#pragma unroll
            for (int i = 0; i < 4; i++) {
                S[i] = mul2(Z[i], Z[i]);                // s = z*z
                T[i] = fma2(S[i], HI2, HC2);            // t = (s - s0)/h
                R[i] = Qt;
            }
        }
#pragma unroll
        for (int m = NP - 1; m >= 0; m--) {
            float2 qm = qs[m];
            unsigned long long Qm = pack2(qm.x, qm.y);  // LDS.64 broadcast
            R[0] = fma2(R[0], T[0], Qm);
            R[1] = fma2(R[1], T[1], Qm);
            R[2] = fma2(R[2], T[2], Qm);
            R[3] = fma2(R[3], T[3], Qm);
        }
        float r[8];
#pragma unroll
        for (int i = 0; i < 4; i++) {
            unsigned long long E = fma2(Z[i], NIL2, R[i]);  // P(t) - z/ln2
            float e0, e1, s0f, s1f;
            unpack2(E, e0, e1);
            unpack2(S[i], s0f, s1f);
            r[2 * i]     = ex2f(fmaf(24.75f, lg2f(s0f), e0));
            r[2 * i + 1] = ex2f(fmaf(24.75f, lg2f(s1f), e1));
        }
        __stcs((float4*)(out + base),     make_float4(r[0], r[1], r[2], r[3]));
        __stcs((float4*)(out + base + 4), make_float4(r[4], r[5], r[6], r[7]));
    } else {
        long long end = ((long long)n < base + EPT) ? (long long)n : base + EPT;
        for (long long i = base; i < end; i++) {
            float z = zin[i];
            float s = z * z;
            float t = fmaf(s, HIF, HCF);
            float rr = tab.q[NP];
            for (int m = NP - 1; m >= 0; m--) rr = fmaf(rr, t, tab.q[m]);
            float e = fmaf(24.75f, lg2f(s), fmaf(z, -1.44269504088896341f, rr));
            out[i] = ex2f(e);
        }
    }
}

extern "C" void kernel_launch(void* const* d_in, const int* in_sizes, int n_in,
                              void* d_out, int out_size) {
    const float* z = (const float*)d_in[0];
    float* o = (float*)d_out;
    int n = in_sizes[0];
    if (n <= 0) return;
    int per_block = TPB * EPT;
    int grid = (n + per_block - 1) / per_block;
    ive_kernel<<<grid, TPB>>>(z, o, n, H_Q);
}